// round 15
// baseline (speedup 1.0000x reference)
#include <cuda_runtime.h>
#include <cuda_fp16.h>
#include <cstdint>

// Problem constants
#define NNODES 100000
#define DDIM   128
#define RREL   3
#define EEDGES 500000
#define NBASIS 2
#define RN     (RREL * NNODES)
#define RE     (RREL * EEDGES)

// ---------------- scratch (device globals) ----------------------------------
__device__ __half g_h0f[(size_t)NNODES * DDIM];   // activations, fp16
__device__ __half g_h1f[(size_t)NNODES * DDIM];
__device__ __half g_c0f[(size_t)NNODES * DDIM];   // basis combos, fp16
__device__ __half g_c1f[(size_t)NNODES * DDIM];
__device__ float g_rdeg[RN];
__device__ int   g_deg [RN];
__device__ int   g_off [RN + 1];
__device__ int   g_cur [RN];
__device__ int   g_part[1024];
__device__ int   g_csr [RE];
__device__ __half g_wthi[128 * 384];   // layer weights [o][k], fp16 (single product)
__device__ __half g_pwhi[128 * 128];   // proj weights [o][k], fp16 hi
__device__ __half g_pwlo[128 * 128];   // proj residual

// ---------------- smem geometry -----------------------------------------------
#define B_PITCH 144
#define B_TILE (128 * B_PITCH)                 // 18432
#define A_PITCH_F 72
#define A_TILE_F32 (128 * A_PITCH_F * 4)       // 36864
#define SMEM_PROJ  (2 * A_TILE_F32 + 2 * B_TILE)   // 110592
#define SMEM_LAYER (3 * B_TILE)                    // 55296

__device__ __forceinline__ uint32_t smem_u32(const void* p) {
    uint32_t a;
    asm("{ .reg .u64 t; cvta.to.shared.u64 t, %1; cvt.u32.u64 %0, t; }" : "=r"(a) : "l"(p));
    return a;
}

__device__ __forceinline__ void cp_async16(uint32_t dst, const void* src, uint32_t sz) {
    asm volatile("cp.async.cg.shared.global [%0], [%1], 16, %2;"
                 :: "r"(dst), "l"(src), "r"(sz));
}
#define CP_COMMIT()  asm volatile("cp.async.commit_group;" ::: "memory")
#define CP_WAIT(n)   asm volatile("cp.async.wait_group %0;" :: "n"(n) : "memory")

__device__ __forceinline__ void mma16816h(float* c, const uint32_t* a, const uint32_t* b) {
    asm volatile(
        "mma.sync.aligned.m16n8k16.row.col.f32.f16.f16.f32 "
        "{%0,%1,%2,%3}, {%4,%5,%6,%7}, {%8,%9}, {%0,%1,%2,%3};\n"
        : "+f"(c[0]), "+f"(c[1]), "+f"(c[2]), "+f"(c[3])
        : "r"(a[0]), "r"(a[1]), "r"(a[2]), "r"(a[3]), "r"(b[0]), "r"(b[1]));
}

__device__ __forceinline__ uint32_t pack_f16x2(float2 f) {
    uint32_t r;
    asm("cvt.rn.f16x2.f32 %0, %1, %2;" : "=r"(r) : "f"(f.y), "f"(f.x));
    return r;
}

// ---------------- fused: proj GEMM + degree histogram ---------------------------
// blocks [0, NPROJ): 128x128 fp16 GEMM, A fp32 in-loop converted, 2-product W.
// blocks [NPROJ, NPROJ+DEG_BLOCKS): edge-degree histogram (backfills SM slots).
#define NPROJ 782
#define DEG_EPB 1536
#define DEG_BLOCKS ((RE + DEG_EPB - 1) / DEG_EPB)   // 977

__global__ __launch_bounds__(128, 2)
void proj_gemm_deg(const float* __restrict__ Af,
                   const __half* __restrict__ whi, const __half* __restrict__ wlo,
                   const float* __restrict__ bias, __half* __restrict__ Cf, int nrows,
                   const int* __restrict__ edge_dst, int* __restrict__ deg) {
    if (blockIdx.x >= NPROJ) {
        int base = (blockIdx.x - NPROJ) * DEG_EPB + threadIdx.x;
#pragma unroll
        for (int j = 0; j < 12; ++j) {
            int i = base + j * 128;
            if (i < RE) {
                int r = i / EEDGES;
                atomicAdd(&deg[r * NNODES + edge_dst[i]], 1);
            }
        }
        return;
    }

    extern __shared__ char smem[];
    constexpr int OFF_A1_ = A_TILE_F32;
    constexpr int OFF_BH  = 2 * A_TILE_F32;
    constexpr int OFF_BL  = 2 * A_TILE_F32 + B_TILE;
    const uint32_t sbase = smem_u32(smem);
    const int tid  = threadIdx.x;
    const int wid  = tid >> 5;
    const int lane = tid & 31;
    const int wm = wid & 1;
    const int wn = wid >> 1;
    const int g  = lane >> 2;
    const int tg = lane & 3;
    const int n0 = blockIdx.x * 128;

    float acc[4][8][4];
#pragma unroll
    for (int mt = 0; mt < 4; mt++)
#pragma unroll
        for (int nt = 0; nt < 8; nt++)
#pragma unroll
            for (int j = 0; j < 4; j++) acc[mt][nt][j] = 0.f;

    auto load_A = [&](int cc) {
        const int kc = (cc & 1) * 64;
        uint32_t dbase = sbase + ((cc & 1) ? OFF_A1_ : 0);
#pragma unroll
        for (int i = 0; i < 16; ++i) {
            int idx = i * 128 + tid;
            int row = idx >> 4;
            int q   = idx & 15;
            int n = n0 + row;
            bool valid = (n < nrows);
            const float* src = Af + (size_t)(valid ? n : 0) * DDIM + kc + q * 4;
            cp_async16(dbase + row * (A_PITCH_F * 4) + q * 16, src, valid ? 16u : 0u);
        }
    };
    auto load_B = [&](int cc) {
#pragma unroll
        for (int i = 0; i < 8; ++i) {
            int idx = i * 128 + tid;
            int n = idx >> 3;
            int q = idx & 7;
            uint32_t boff = n * B_PITCH + q * 16;
            size_t goff = (size_t)n * DDIM + cc * 64 + q * 8;
            cp_async16(sbase + OFF_BH + boff, whi + goff, 16);
            cp_async16(sbase + OFF_BL + boff, wlo + goff, 16);
        }
    };

    const int arow_f = (wm * 64 + g) * A_PITCH_F + 2 * tg;
    const int brow   = (wn * 64 + g) * B_PITCH + tg * 4;

    load_A(0);
    CP_COMMIT();
#pragma unroll 1
    for (int c = 0; c < 2; ++c) {
        load_B(c);
        CP_COMMIT();
        if (c + 1 < 2) {
            load_A(c + 1);
            CP_COMMIT();
            CP_WAIT(1);
        } else {
            CP_WAIT(0);
        }
        __syncthreads();
        const char* Ab = smem + ((c & 1) ? OFF_A1_ : 0);
#pragma unroll
        for (int ks = 0; ks < 4; ++ks) {
            uint32_t a[4][4], bfr[8][2];
#pragma unroll
            for (int mt = 0; mt < 4; ++mt) {
                int fb = arow_f + mt * 16 * A_PITCH_F + ks * 16;
                float2 f0 = *reinterpret_cast<const float2*>(Ab + fb * 4);
                float2 f1 = *reinterpret_cast<const float2*>(Ab + (fb + 8 * A_PITCH_F) * 4);
                float2 f2 = *reinterpret_cast<const float2*>(Ab + (fb + 8) * 4);
                float2 f3 = *reinterpret_cast<const float2*>(Ab + (fb + 8 * A_PITCH_F + 8) * 4);
                a[mt][0] = pack_f16x2(f0);
                a[mt][1] = pack_f16x2(f1);
                a[mt][2] = pack_f16x2(f2);
                a[mt][3] = pack_f16x2(f3);
            }
#pragma unroll
            for (int nt = 0; nt < 8; ++nt) {
                int bb = brow + nt * (8 * B_PITCH) + ks * 32;
                bfr[nt][0] = *(const uint32_t*)(smem + OFF_BH + bb);
                bfr[nt][1] = *(const uint32_t*)(smem + OFF_BH + bb + 16);
            }
#pragma unroll
            for (int mt = 0; mt < 4; ++mt)
#pragma unroll
                for (int nt = 0; nt < 8; ++nt)
                    mma16816h(acc[mt][nt], a[mt], bfr[nt]);    // A * Whi
#pragma unroll
            for (int nt = 0; nt < 8; ++nt) {
                int bb = brow + nt * (8 * B_PITCH) + ks * 32;
                bfr[nt][0] = *(const uint32_t*)(smem + OFF_BL + bb);
                bfr[nt][1] = *(const uint32_t*)(smem + OFF_BL + bb + 16);
            }
#pragma unroll
            for (int mt = 0; mt < 4; ++mt)
#pragma unroll
                for (int nt = 0; nt < 8; ++nt)
                    mma16816h(acc[mt][nt], a[mt], bfr[nt]);    // A * Wlo
        }
        __syncthreads();
    }

    // epilogue: bias (no relu), fp16 out
#pragma unroll
    for (int nt = 0; nt < 8; ++nt) {
        int col = wn * 64 + nt * 8 + 2 * tg;
        float bz0 = __ldg(bias + col);
        float bz1 = __ldg(bias + col + 1);
#pragma unroll
        for (int mt = 0; mt < 4; ++mt) {
            int row0 = n0 + wm * 64 + mt * 16 + g;
            int row1 = row0 + 8;
            if (row0 < nrows)
                *reinterpret_cast<uint32_t*>(Cf + (size_t)row0 * DDIM + col) =
                    pack_f16x2(make_float2(acc[mt][nt][0] + bz0, acc[mt][nt][1] + bz1));
            if (row1 < nrows)
                *reinterpret_cast<uint32_t*>(Cf + (size_t)row1 * DDIM + col) =
                    pack_f16x2(make_float2(acc[mt][nt][2] + bz0, acc[mt][nt][3] + bz1));
        }
    }
}

// ---------------- layer GEMM (R12-proven: double-buffered A, single B) ----------
template <bool OUTF16>
__global__ __launch_bounds__(128, 2)
void tc_gemm_layer(const __half* __restrict__ A0, const __half* __restrict__ A1,
                   const __half* __restrict__ A2,
                   const __half* __restrict__ whi,
                   const float* __restrict__ bias, float* __restrict__ C,
                   __half* __restrict__ Cf, int nrows) {
    extern __shared__ char smem[];
    constexpr int OFF_A1_ = B_TILE;
    constexpr int OFF_BH  = 2 * B_TILE;
    const uint32_t sbase = smem_u32(smem);
    const int tid  = threadIdx.x;
    const int wid  = tid >> 5;
    const int lane = tid & 31;
    const int wm = wid & 1;
    const int wn = wid >> 1;
    const int g  = lane >> 2;
    const int tg = lane & 3;
    const int n0 = blockIdx.x * 128;
    const int KSTRIDE = 384;
    const __half* Aseg[3] = {A0, A1, A2};

    float acc[4][8][4];
#pragma unroll
    for (int mt = 0; mt < 4; mt++)
#pragma unroll
        for (int nt = 0; nt < 8; nt++)
#pragma unroll
            for (int j = 0; j < 4; j++) acc[mt][nt][j] = 0.f;

    auto load_A = [&](int cc) {
        const int kc = (cc & 1) * 64;
        const __half* A = Aseg[cc >> 1];
        uint32_t dbase = sbase + ((cc & 1) ? OFF_A1_ : 0);
#pragma unroll
        for (int i = 0; i < 8; ++i) {
            int idx = i * 128 + tid;
            int row = idx >> 3;
            int q   = idx & 7;
            int n = n0 + row;
            bool valid = (n < nrows);
            const __half* src = A + (size_t)(valid ? n : 0) * DDIM + kc + q * 8;
            cp_async16(dbase + row * B_PITCH + q * 16, src, valid ? 16u : 0u);
        }
    };
    auto load_B = [&](int cc) {
#pragma unroll
        for (int i = 0; i < 8; ++i) {
            int idx = i * 128 + tid;
            int n = idx >> 3;
            int q = idx & 7;
            size_t goff = (size_t)n * KSTRIDE + cc * 64 + q * 8;
            cp_async16(sbase + OFF_BH + n * B_PITCH + q * 16, whi + goff, 16);
        }
    };

    const int arow_b = (wm * 64 + g) * B_PITCH + tg * 4;
    const int brow   = (wn * 64 + g) * B_PITCH + tg * 4;

    load_A(0);
    CP_COMMIT();

#pragma unroll 1
    for (int c = 0; c < 6; ++c) {
        load_B(c);
        CP_COMMIT();
        if (c + 1 < 6) {
            load_A(c + 1);
            CP_COMMIT();
            CP_WAIT(1);
        } else {
            CP_WAIT(0);
        }
        __syncthreads();

        const char* Ab = smem + ((c & 1) ? OFF_A1_ : 0);

#pragma unroll
        for (int ks = 0; ks < 4; ++ks) {
            uint32_t a[4][4], bfr[8][2];
#pragma unroll
            for (int mt = 0; mt < 4; ++mt) {
                int bb = arow_b + mt * 16 * B_PITCH + ks * 32;
                a[mt][0] = *(const uint32_t*)(Ab + bb);
                a[mt][1] = *(const uint32_t*)(Ab + bb + 8 * B_PITCH);
                a[mt][2] = *(const uint32_t*)(Ab + bb + 16);
                a[mt][3] = *(const uint32_t*)(Ab + bb + 8 * B_PITCH + 16);
            }
#pragma unroll
            for (int nt = 0; nt < 8; ++nt) {
                int bb = brow + nt * (8 * B_PITCH) + ks * 32;
                bfr[nt][0] = *(const uint32_t*)(smem + OFF_BH + bb);
                bfr[nt][1] = *(const uint32_t*)(smem + OFF_BH + bb + 16);
            }
#pragma unroll
            for (int mt = 0; mt < 4; ++mt)
#pragma unroll
                for (int nt = 0; nt < 8; ++nt)
                    mma16816h(acc[mt][nt], a[mt], bfr[nt]);
        }
        __syncthreads();
    }

    // epilogue: bias + relu
#pragma unroll
    for (int nt = 0; nt < 8; ++nt) {
        int col = wn * 64 + nt * 8 + 2 * tg;
        float bz0 = __ldg(bias + col);
        float bz1 = __ldg(bias + col + 1);
#pragma unroll
        for (int mt = 0; mt < 4; ++mt) {
            int row0 = n0 + wm * 64 + mt * 16 + g;
            int row1 = row0 + 8;
            float v0 = fmaxf(acc[mt][nt][0] + bz0, 0.f);
            float v1 = fmaxf(acc[mt][nt][1] + bz1, 0.f);
            float v2 = fmaxf(acc[mt][nt][2] + bz0, 0.f);
            float v3 = fmaxf(acc[mt][nt][3] + bz1, 0.f);
            if (row0 < nrows) {
                if constexpr (OUTF16)
                    *reinterpret_cast<uint32_t*>(Cf + (size_t)row0 * DDIM + col) =
                        pack_f16x2(make_float2(v0, v1));
                else
                    *reinterpret_cast<float2*>(C + (size_t)row0 * DDIM + col) = make_float2(v0, v1);
            }
            if (row1 < nrows) {
                if constexpr (OUTF16)
                    *reinterpret_cast<uint32_t*>(Cf + (size_t)row1 * DDIM + col) =
                        pack_f16x2(make_float2(v2, v3));
                else
                    *reinterpret_cast<float2*>(C + (size_t)row1 * DDIM + col) = make_float2(v2, v3);
            }
        }
    }
}

// ---------------- fused: proj weight build + deg zero ---------------------------
#define PWT_BLOCKS 64                               // 128*128 / 256
#define ZERO_BLOCKS ((RN + 2047) / 2048)            // 147 (256 thr x 8)
__global__ void wtproj_zero(const float* __restrict__ projw,
                            __half* __restrict__ pwhi, __half* __restrict__ pwlo,
                            int* __restrict__ deg) {
    int b = blockIdx.x;
    if (b < PWT_BLOCKS) {
        int i = b * 256 + threadIdx.x;
        int o = i >> 7;
        int k = i & 127;
        float v = projw[k * DDIM + o];
        __half h = __float2half_rn(v);
        pwhi[i] = h;
        pwlo[i] = __float2half_rn(v - __half2float(h));
        return;
    }
    int base = (b - PWT_BLOCKS) * 2048 + threadIdx.x;
#pragma unroll
    for (int j = 0; j < 8; ++j) {
        int i = base + j * 256;
        if (i < RN) deg[i] = 0;
    }
}

// ---------------- scan kernels ---------------------------------------------------
#define SCAN_BLOCKS ((RN + 1023) / 1024)            // 293

__global__ void scan_reduce(const int* __restrict__ deg, int* __restrict__ part, int n) {
    __shared__ int sm[256];
    int b = blockIdx.x, t = threadIdx.x;
    int i0 = b * 1024 + t * 4;
    int s = 0;
#pragma unroll
    for (int j = 0; j < 4; ++j) { int i = i0 + j; if (i < n) s += deg[i]; }
    sm[t] = s; __syncthreads();
    for (int st = 128; st > 0; st >>= 1) { if (t < st) sm[t] += sm[t + st]; __syncthreads(); }
    if (t == 0) part[b] = sm[0];
}

// final scan with inline exclusive prefix over raw partials (replaces scan_partials)
__global__ void scan_final2(const int* __restrict__ deg, const int* __restrict__ part,
                            int* __restrict__ off, int* __restrict__ cur,
                            float* __restrict__ rdeg, int n, int nblocks) {
    __shared__ int sp[256];
    __shared__ int sm[256];
    int b = blockIdx.x, t = threadIdx.x;
    if (b == 0 && t == 0) off[RN] = RE;
    // exclusive prefix: sum part[i] for i < b (nblocks <= 512)
    int v0 = (t < nblocks && t < b) ? part[t] : 0;
    int v1 = (t + 256 < nblocks && t + 256 < b) ? part[t + 256] : 0;
    sp[t] = v0 + v1; __syncthreads();
    for (int st = 128; st > 0; st >>= 1) { if (t < st) sp[t] += sp[t + st]; __syncthreads(); }
    int base0 = sp[0];

    int i0 = b * 1024 + t * 4;
    int v[4]; int s = 0;
#pragma unroll
    for (int j = 0; j < 4; ++j) { int i = i0 + j; v[j] = (i < n) ? deg[i] : 0; s += v[j]; }
    sm[t] = s; __syncthreads();
    for (int st = 1; st < 256; st <<= 1) {
        int add = (t >= st) ? sm[t - st] : 0;
        __syncthreads();
        sm[t] += add;
        __syncthreads();
    }
    int base = base0 + sm[t] - s;
#pragma unroll
    for (int j = 0; j < 4; ++j) {
        int i = i0 + j;
        if (i < n) {
            off[i] = base; cur[i] = base; base += v[j];
            rdeg[i] = 1.0f / fmaxf((float)v[j], 1.0f);
        }
    }
}

__global__ void fill_csr(const int* __restrict__ src, const int* __restrict__ dst,
                         int* __restrict__ cur, int* __restrict__ csr) {
    int i = blockIdx.x * blockDim.x + threadIdx.x;
    if (i >= RE) return;
    int r = i / EEDGES;
    int slot = atomicAdd(&cur[r * NNODES + dst[i]], 1);
    csr[slot] = src[i];
}

// ---------------- gather-aggregate (R8 structure) + layer wt build -------------
#define GATHER_BLOCKS ((NNODES * 32 + 255) / 256)
__global__ __launch_bounds__(256)
void gather_combo_wt(const __half* __restrict__ h, const int* __restrict__ off,
                     const int* __restrict__ csr, const float* __restrict__ rdeg,
                     const float* __restrict__ coeff,
                     __half* __restrict__ c0, __half* __restrict__ c1,
                     const float* __restrict__ basis, const float* __restrict__ loopw,
                     __half* __restrict__ whi) {
    int b = blockIdx.x;
    if (b >= GATHER_BLOCKS) {
        int i = (b - GATHER_BLOCKS) * 256 + threadIdx.x;   // 128*384
        if (i < 128 * 384) {
            int o = i / 384;
            int k = i - o * 384;
            int seg = k >> 7;
            int kk = k & 127;
            float v = (seg < 2) ? basis[(size_t)seg * DDIM * DDIM + kk * DDIM + o]
                                : loopw[kk * DDIM + o];
            whi[i] = __float2half_rn(v);
        }
        return;
    }
    int gw = (int)(((unsigned)b * 256u + threadIdx.x) >> 5);
    int lane = threadIdx.x & 31;
    if (gw >= NNODES) return;
    float4 a0 = make_float4(0.f, 0.f, 0.f, 0.f);
    float4 a1 = a0;
#pragma unroll
    for (int r = 0; r < RREL; ++r) {
        int base = r * NNODES + gw;
        int s0 = __ldg(off + base), s1 = __ldg(off + base + 1);
        float4 sum = make_float4(0.f, 0.f, 0.f, 0.f);
        int e = s0;
        for (; e + 2 <= s1; e += 2) {
            int sa = __ldg(csr + e), sb = __ldg(csr + e + 1);
            uint2 ua = *reinterpret_cast<const uint2*>(h + (size_t)sa * DDIM + lane * 4);
            uint2 ub = *reinterpret_cast<const uint2*>(h + (size_t)sb * DDIM + lane * 4);
            float2 fa0 = __half22float2(*reinterpret_cast<__half2*>(&ua.x));
            float2 fa1 = __half22float2(*reinterpret_cast<__half2*>(&ua.y));
            float2 fb0 = __half22float2(*reinterpret_cast<__half2*>(&ub.x));
            float2 fb1 = __half22float2(*reinterpret_cast<__half2*>(&ub.y));
            sum.x += fa0.x + fb0.x; sum.y += fa0.y + fb0.y;
            sum.z += fa1.x + fb1.x; sum.w += fa1.y + fb1.y;
        }
        if (e < s1) {
            int sa = __ldg(csr + e);
            uint2 ua = *reinterpret_cast<const uint2*>(h + (size_t)sa * DDIM + lane * 4);
            float2 fa0 = __half22float2(*reinterpret_cast<__half2*>(&ua.x));
            float2 fa1 = __half22float2(*reinterpret_cast<__half2*>(&ua.y));
            sum.x += fa0.x; sum.y += fa0.y; sum.z += fa1.x; sum.w += fa1.y;
        }
        float w  = __ldg(rdeg + base);
        float k0 = __ldg(coeff + r * NBASIS)     * w;
        float k1 = __ldg(coeff + r * NBASIS + 1) * w;
        a0.x += k0 * sum.x; a0.y += k0 * sum.y; a0.z += k0 * sum.z; a0.w += k0 * sum.w;
        a1.x += k1 * sum.x; a1.y += k1 * sum.y; a1.z += k1 * sum.z; a1.w += k1 * sum.w;
    }
    uint2 o0, o1;
    o0.x = pack_f16x2(make_float2(a0.x, a0.y));
    o0.y = pack_f16x2(make_float2(a0.z, a0.w));
    o1.x = pack_f16x2(make_float2(a1.x, a1.y));
    o1.y = pack_f16x2(make_float2(a1.z, a1.w));
    *reinterpret_cast<uint2*>(c0 + (size_t)gw * DDIM + lane * 4) = o0;
    *reinterpret_cast<uint2*>(c1 + (size_t)gw * DDIM + lane * 4) = o1;
}

// ---------------- launch ----------------------------------------------------------
extern "C" void kernel_launch(void* const* d_in, const int* in_sizes, int n_in,
                              void* d_out, int out_size) {
    const float* x        = (const float*)d_in[0];
    const int*   edge_src = (const int*)  d_in[1];
    const int*   edge_dst = (const int*)  d_in[2];
    const float* proj_w   = (const float*)d_in[3];
    const float* proj_b   = (const float*)d_in[4];
    const float* basis1   = (const float*)d_in[5];
    const float* coeff1   = (const float*)d_in[6];
    const float* bias1    = (const float*)d_in[7];
    const float* loop1    = (const float*)d_in[8];
    const float* basis2   = (const float*)d_in[9];
    const float* coeff2   = (const float*)d_in[10];
    const float* bias2    = (const float*)d_in[11];
    const float* loop2    = (const float*)d_in[12];
    float* out = (float*)d_out;

    float *rdeg;
    int *deg, *off, *cur, *part, *csr;
    __half *h0f, *h1f, *c0f, *c1f, *wthi, *pwhi, *pwlo;
    cudaGetSymbolAddress((void**)&h0f,  g_h0f);
    cudaGetSymbolAddress((void**)&h1f,  g_h1f);
    cudaGetSymbolAddress((void**)&c0f,  g_c0f);
    cudaGetSymbolAddress((void**)&c1f,  g_c1f);
    cudaGetSymbolAddress((void**)&rdeg, g_rdeg);
    cudaGetSymbolAddress((void**)&deg,  g_deg);
    cudaGetSymbolAddress((void**)&off,  g_off);
    cudaGetSymbolAddress((void**)&cur,  g_cur);
    cudaGetSymbolAddress((void**)&part, g_part);
    cudaGetSymbolAddress((void**)&csr,  g_csr);
    cudaGetSymbolAddress((void**)&wthi, g_wthi);
    cudaGetSymbolAddress((void**)&pwhi, g_pwhi);
    cudaGetSymbolAddress((void**)&pwlo, g_pwlo);

    cudaFuncSetAttribute(proj_gemm_deg,
                         cudaFuncAttributeMaxDynamicSharedMemorySize, SMEM_PROJ);
    cudaFuncSetAttribute(tc_gemm_layer<true>,
                         cudaFuncAttributeMaxDynamicSharedMemorySize, SMEM_LAYER);
    cudaFuncSetAttribute(tc_gemm_layer<false>,
                         cudaFuncAttributeMaxDynamicSharedMemorySize, SMEM_LAYER);

    const int wt_blocks = (128 * 384 + 255) / 256;          // 192

    // 1. proj weights + zero deg (fused hetero blocks)
    wtproj_zero<<<PWT_BLOCKS + ZERO_BLOCKS, 256>>>(proj_w, pwhi, pwlo, deg);
    // 2. proj GEMM + degree histogram (fused hetero blocks)
    proj_gemm_deg<<<NPROJ + DEG_BLOCKS, 128, SMEM_PROJ>>>(
        x, pwhi, pwlo, proj_b, h0f, NNODES, edge_dst, deg);
    // 3-5. CSR build
    scan_reduce<<<SCAN_BLOCKS, 256>>>(deg, part, RN);
    scan_final2<<<SCAN_BLOCKS, 256>>>(deg, part, off, cur, rdeg, RN, SCAN_BLOCKS);
    fill_csr<<<(RE + 255) / 256, 256>>>(edge_src, edge_dst, cur, csr);

    // ---- layer 1 ----
    gather_combo_wt<<<GATHER_BLOCKS + wt_blocks, 256>>>(h0f, off, csr, rdeg, coeff1,
                                                        c0f, c1f, basis1, loop1, wthi);
    tc_gemm_layer<true><<<NPROJ, 128, SMEM_LAYER>>>(c0f, c1f, h0f, wthi,
                                                    bias1, nullptr, h1f, NNODES);

    // ---- layer 2 ----
    gather_combo_wt<<<GATHER_BLOCKS + wt_blocks, 256>>>(h1f, off, csr, rdeg, coeff2,
                                                        c0f, c1f, basis2, loop2, wthi);
    tc_gemm_layer<false><<<NPROJ, 128, SMEM_LAYER>>>(c0f, c1f, h1f, wthi,
                                                     bias2, out, nullptr, NNODES);
}

// round 16
// speedup vs baseline: 1.0612x; 1.0612x over previous
#include <cuda_runtime.h>
#include <cuda_fp16.h>
#include <cstdint>

// Problem constants
#define NNODES 100000
#define DDIM   128
#define RREL   3
#define EEDGES 500000
#define NBASIS 2
#define RN     (RREL * NNODES)
#define RE     (RREL * EEDGES)

// ---------------- scratch (device globals) ----------------------------------
__device__ __half g_h0f[(size_t)NNODES * DDIM];   // activations, fp16
__device__ __half g_h1f[(size_t)NNODES * DDIM];
__device__ __half g_c0f[(size_t)NNODES * DDIM];   // basis combos, fp16
__device__ __half g_c1f[(size_t)NNODES * DDIM];
__device__ float g_rdeg[RN];
__device__ int   g_deg [RN];
__device__ int   g_off [RN + 1];
__device__ int   g_cur [RN];
__device__ int   g_part[1024];
__device__ int   g_csr [RE];
__device__ __half g_wthi[128 * 384];   // layer weights [o][k], fp16
__device__ __half g_pwhi[128 * 128];   // proj weights [o][k], fp16

// ---------------- smem geometry -----------------------------------------------
#define B_PITCH 144
#define B_TILE (128 * B_PITCH)                 // 18432
#define A_PITCH_F 72
#define A_TILE_F32 (128 * A_PITCH_F * 4)       // 36864
#define SMEM_PROJ  (2 * A_TILE_F32 + B_TILE)   // 92160
#define SMEM_LAYER (3 * B_TILE)                // 55296

__device__ __forceinline__ uint32_t smem_u32(const void* p) {
    uint32_t a;
    asm("{ .reg .u64 t; cvta.to.shared.u64 t, %1; cvt.u32.u64 %0, t; }" : "=r"(a) : "l"(p));
    return a;
}

__device__ __forceinline__ void cp_async16(uint32_t dst, const void* src, uint32_t sz) {
    asm volatile("cp.async.cg.shared.global [%0], [%1], 16, %2;"
                 :: "r"(dst), "l"(src), "r"(sz));
}
#define CP_COMMIT()  asm volatile("cp.async.commit_group;" ::: "memory")
#define CP_WAIT(n)   asm volatile("cp.async.wait_group %0;" :: "n"(n) : "memory")

__device__ __forceinline__ void mma16816h(float* c, const uint32_t* a, const uint32_t* b) {
    asm volatile(
        "mma.sync.aligned.m16n8k16.row.col.f32.f16.f16.f32 "
        "{%0,%1,%2,%3}, {%4,%5,%6,%7}, {%8,%9}, {%0,%1,%2,%3};\n"
        : "+f"(c[0]), "+f"(c[1]), "+f"(c[2]), "+f"(c[3])
        : "r"(a[0]), "r"(a[1]), "r"(a[2]), "r"(a[3]), "r"(b[0]), "r"(b[1]));
}

__device__ __forceinline__ uint32_t pack_f16x2(float2 f) {
    uint32_t r;
    asm("cvt.rn.f16x2.f32 %0, %1, %2;" : "=r"(r) : "f"(f.y), "f"(f.x));
    return r;
}

// ---------------- fp16 tensor-core GEMM (single W product) ----------------------
// F32A (proj): A = one fp32 segment, converted to fp16 in-loop. NSEG must be 1.
// !F32A (layers): A = NSEG fp16 segments.
// OUTF16: write fp16 Cf; else fp32 C.
template <bool RELU, int NSEG, bool F32A, bool OUTF16>
__global__ __launch_bounds__(128, 2)
void tc_gemm(const float* __restrict__ Af,
             const __half* __restrict__ A0, const __half* __restrict__ A1,
             const __half* __restrict__ A2,
             const __half* __restrict__ whi,
             const float* __restrict__ bias, float* __restrict__ C,
             __half* __restrict__ Cf, int nrows) {
    extern __shared__ char smem[];
    constexpr int ATILE   = F32A ? A_TILE_F32 : B_TILE;
    constexpr int OFF_A1_ = ATILE;
    constexpr int OFF_BH  = 2 * ATILE;
    const uint32_t sbase = smem_u32(smem);
    const int tid  = threadIdx.x;
    const int wid  = tid >> 5;
    const int lane = tid & 31;
    const int wm = wid & 1;
    const int wn = wid >> 1;
    const int g  = lane >> 2;
    const int tg = lane & 3;
    const int n0 = blockIdx.x * 128;
    const int KSTRIDE = NSEG * 128;
    const __half* Aseg[3] = {A0, A1, A2};
    const int NCHUNK = 2 * NSEG;

    float acc[4][8][4];
#pragma unroll
    for (int mt = 0; mt < 4; mt++)
#pragma unroll
        for (int nt = 0; nt < 8; nt++)
#pragma unroll
            for (int j = 0; j < 4; j++) acc[mt][nt][j] = 0.f;

    auto load_A = [&](int cc) {
        const int kc = (cc & 1) * 64;
        uint32_t dbase = sbase + ((cc & 1) ? OFF_A1_ : 0);
        if constexpr (F32A) {
#pragma unroll
            for (int i = 0; i < 16; ++i) {
                int idx = i * 128 + tid;
                int row = idx >> 4;
                int q   = idx & 15;
                int n = n0 + row;
                bool valid = (n < nrows);
                const float* src = Af + (size_t)(valid ? n : 0) * DDIM + kc + q * 4;
                cp_async16(dbase + row * (A_PITCH_F * 4) + q * 16, src, valid ? 16u : 0u);
            }
        } else {
            const __half* A = Aseg[cc >> 1];
#pragma unroll
            for (int i = 0; i < 8; ++i) {
                int idx = i * 128 + tid;
                int row = idx >> 3;
                int q   = idx & 7;
                int n = n0 + row;
                bool valid = (n < nrows);
                const __half* src = A + (size_t)(valid ? n : 0) * DDIM + kc + q * 8;
                cp_async16(dbase + row * B_PITCH + q * 16, src, valid ? 16u : 0u);
            }
        }
    };

    auto load_B = [&](int cc) {
#pragma unroll
        for (int i = 0; i < 8; ++i) {
            int idx = i * 128 + tid;
            int n = idx >> 3;
            int q = idx & 7;
            size_t goff = (size_t)n * KSTRIDE + cc * 64 + q * 8;
            cp_async16(sbase + OFF_BH + n * B_PITCH + q * 16, whi + goff, 16);
        }
    };

    const int arow_f = (wm * 64 + g) * A_PITCH_F + 2 * tg;
    const int arow_b = (wm * 64 + g) * B_PITCH + tg * 4;
    const int brow   = (wn * 64 + g) * B_PITCH + tg * 4;

    load_A(0);
    CP_COMMIT();

#pragma unroll 1
    for (int c = 0; c < NCHUNK; ++c) {
        load_B(c);
        CP_COMMIT();
        if (c + 1 < NCHUNK) {
            load_A(c + 1);
            CP_COMMIT();
            CP_WAIT(1);
        } else {
            CP_WAIT(0);
        }
        __syncthreads();

        const char* Ab = smem + ((c & 1) ? OFF_A1_ : 0);

#pragma unroll
        for (int ks = 0; ks < 4; ++ks) {
            uint32_t a[4][4], bfr[8][2];
            if constexpr (F32A) {
#pragma unroll
                for (int mt = 0; mt < 4; ++mt) {
                    int fb = arow_f + mt * 16 * A_PITCH_F + ks * 16;
                    float2 f0 = *reinterpret_cast<const float2*>(Ab + fb * 4);
                    float2 f1 = *reinterpret_cast<const float2*>(Ab + (fb + 8 * A_PITCH_F) * 4);
                    float2 f2 = *reinterpret_cast<const float2*>(Ab + (fb + 8) * 4);
                    float2 f3 = *reinterpret_cast<const float2*>(Ab + (fb + 8 * A_PITCH_F + 8) * 4);
                    a[mt][0] = pack_f16x2(f0);
                    a[mt][1] = pack_f16x2(f1);
                    a[mt][2] = pack_f16x2(f2);
                    a[mt][3] = pack_f16x2(f3);
                }
            } else {
#pragma unroll
                for (int mt = 0; mt < 4; ++mt) {
                    int bb = arow_b + mt * 16 * B_PITCH + ks * 32;
                    a[mt][0] = *(const uint32_t*)(Ab + bb);
                    a[mt][1] = *(const uint32_t*)(Ab + bb + 8 * B_PITCH);
                    a[mt][2] = *(const uint32_t*)(Ab + bb + 16);
                    a[mt][3] = *(const uint32_t*)(Ab + bb + 8 * B_PITCH + 16);
                }
            }
#pragma unroll
            for (int nt = 0; nt < 8; ++nt) {
                int bb = brow + nt * (8 * B_PITCH) + ks * 32;
                bfr[nt][0] = *(const uint32_t*)(smem + OFF_BH + bb);
                bfr[nt][1] = *(const uint32_t*)(smem + OFF_BH + bb + 16);
            }
#pragma unroll
            for (int mt = 0; mt < 4; ++mt)
#pragma unroll
                for (int nt = 0; nt < 8; ++nt)
                    mma16816h(acc[mt][nt], a[mt], bfr[nt]);
        }
        __syncthreads();
    }

    // ---- epilogue: bias + relu ----
#pragma unroll
    for (int nt = 0; nt < 8; ++nt) {
        int col = wn * 64 + nt * 8 + 2 * tg;
        float bz0 = __ldg(bias + col);
        float bz1 = __ldg(bias + col + 1);
#pragma unroll
        for (int mt = 0; mt < 4; ++mt) {
            int row0 = n0 + wm * 64 + mt * 16 + g;
            int row1 = row0 + 8;
            float v0 = acc[mt][nt][0] + bz0, v1 = acc[mt][nt][1] + bz1;
            float v2 = acc[mt][nt][2] + bz0, v3 = acc[mt][nt][3] + bz1;
            if (RELU) {
                v0 = fmaxf(v0, 0.f); v1 = fmaxf(v1, 0.f);
                v2 = fmaxf(v2, 0.f); v3 = fmaxf(v3, 0.f);
            }
            if (row0 < nrows) {
                if constexpr (OUTF16)
                    *reinterpret_cast<uint32_t*>(Cf + (size_t)row0 * DDIM + col) =
                        pack_f16x2(make_float2(v0, v1));
                else
                    *reinterpret_cast<float2*>(C + (size_t)row0 * DDIM + col) = make_float2(v0, v1);
            }
            if (row1 < nrows) {
                if constexpr (OUTF16)
                    *reinterpret_cast<uint32_t*>(Cf + (size_t)row1 * DDIM + col) =
                        pack_f16x2(make_float2(v2, v3));
                else
                    *reinterpret_cast<float2*>(C + (size_t)row1 * DDIM + col) = make_float2(v2, v3);
            }
        }
    }
}

// ---------------- fused: proj weight build (fp16) + deg zero --------------------
#define PWT_BLOCKS 64                               // 128*128 / 256
#define ZERO_BLOCKS ((RN + 2047) / 2048)            // 147
__global__ void wtproj_zero(const float* __restrict__ projw,
                            __half* __restrict__ pwhi, int* __restrict__ deg) {
    int b = blockIdx.x;
    if (b < PWT_BLOCKS) {
        int i = b * 256 + threadIdx.x;
        int o = i >> 7;
        int k = i & 127;
        pwhi[i] = __float2half_rn(projw[k * DDIM + o]);
        return;
    }
    int base = (b - PWT_BLOCKS) * 2048 + threadIdx.x;
#pragma unroll
    for (int j = 0; j < 8; ++j) {
        int i = base + j * 256;
        if (i < RN) deg[i] = 0;
    }
}

__global__ void deg_count_kernel(const int* __restrict__ dst, int* __restrict__ deg) {
    int i = blockIdx.x * blockDim.x + threadIdx.x;
    if (i >= RE) return;
    int r = i / EEDGES;
    atomicAdd(&deg[r * NNODES + dst[i]], 1);
}

// ---------------- scan: 2 kernels (reduce + final with inline partial scan) ------
#define SCAN_BLOCKS ((RN + 1023) / 1024)            // 293

__global__ void scan_reduce(const int* __restrict__ deg, int* __restrict__ part, int n) {
    __shared__ int sm[256];
    int b = blockIdx.x, t = threadIdx.x;
    int i0 = b * 1024 + t * 4;
    int s = 0;
#pragma unroll
    for (int j = 0; j < 4; ++j) { int i = i0 + j; if (i < n) s += deg[i]; }
    sm[t] = s; __syncthreads();
    for (int st = 128; st > 0; st >>= 1) { if (t < st) sm[t] += sm[t + st]; __syncthreads(); }
    if (t == 0) part[b] = sm[0];
}

__global__ void scan_final2(const int* __restrict__ deg, const int* __restrict__ part,
                            int* __restrict__ off, int* __restrict__ cur,
                            float* __restrict__ rdeg, int n, int nblocks) {
    __shared__ int sp[256];
    __shared__ int sm[256];
    int b = blockIdx.x, t = threadIdx.x;
    if (b == 0 && t == 0) off[RN] = RE;
    int v0 = (t < nblocks && t < b) ? part[t] : 0;
    int v1 = (t + 256 < nblocks && t + 256 < b) ? part[t + 256] : 0;
    sp[t] = v0 + v1; __syncthreads();
    for (int st = 128; st > 0; st >>= 1) { if (t < st) sp[t] += sp[t + st]; __syncthreads(); }
    int base0 = sp[0];

    int i0 = b * 1024 + t * 4;
    int v[4]; int s = 0;
#pragma unroll
    for (int j = 0; j < 4; ++j) { int i = i0 + j; v[j] = (i < n) ? deg[i] : 0; s += v[j]; }
    sm[t] = s; __syncthreads();
    for (int st = 1; st < 256; st <<= 1) {
        int add = (t >= st) ? sm[t - st] : 0;
        __syncthreads();
        sm[t] += add;
        __syncthreads();
    }
    int base = base0 + sm[t] - s;
#pragma unroll
    for (int j = 0; j < 4; ++j) {
        int i = i0 + j;
        if (i < n) {
            off[i] = base; cur[i] = base; base += v[j];
            rdeg[i] = 1.0f / fmaxf((float)v[j], 1.0f);
        }
    }
}

__global__ void fill_csr(const int* __restrict__ src, const int* __restrict__ dst,
                         int* __restrict__ cur, int* __restrict__ csr) {
    int i = blockIdx.x * blockDim.x + threadIdx.x;
    if (i >= RE) return;
    int r = i / EEDGES;
    int slot = atomicAdd(&cur[r * NNODES + dst[i]], 1);
    csr[slot] = src[i];
}

// ---------------- gather-aggregate (R8 structure) + layer wt build -------------
#define GATHER_BLOCKS ((NNODES * 32 + 255) / 256)
__global__ __launch_bounds__(256)
void gather_combo_wt(const __half* __restrict__ h, const int* __restrict__ off,
                     const int* __restrict__ csr, const float* __restrict__ rdeg,
                     const float* __restrict__ coeff,
                     __half* __restrict__ c0, __half* __restrict__ c1,
                     const float* __restrict__ basis, const float* __restrict__ loopw,
                     __half* __restrict__ whi) {
    int b = blockIdx.x;
    if (b >= GATHER_BLOCKS) {
        int i = (b - GATHER_BLOCKS) * 256 + threadIdx.x;   // 128*384
        if (i < 128 * 384) {
            int o = i / 384;
            int k = i - o * 384;
            int seg = k >> 7;
            int kk = k & 127;
            float v = (seg < 2) ? basis[(size_t)seg * DDIM * DDIM + kk * DDIM + o]
                                : loopw[kk * DDIM + o];
            whi[i] = __float2half_rn(v);
        }
        return;
    }
    int gw = (int)(((unsigned)b * 256u + threadIdx.x) >> 5);
    int lane = threadIdx.x & 31;
    if (gw >= NNODES) return;
    float4 a0 = make_float4(0.f, 0.f, 0.f, 0.f);
    float4 a1 = a0;
#pragma unroll
    for (int r = 0; r < RREL; ++r) {
        int base = r * NNODES + gw;
        int s0 = __ldg(off + base), s1 = __ldg(off + base + 1);
        float4 sum = make_float4(0.f, 0.f, 0.f, 0.f);
        int e = s0;
        for (; e + 2 <= s1; e += 2) {
            int sa = __ldg(csr + e), sb = __ldg(csr + e + 1);
            uint2 ua = *reinterpret_cast<const uint2*>(h + (size_t)sa * DDIM + lane * 4);
            uint2 ub = *reinterpret_cast<const uint2*>(h + (size_t)sb * DDIM + lane * 4);
            float2 fa0 = __half22float2(*reinterpret_cast<__half2*>(&ua.x));
            float2 fa1 = __half22float2(*reinterpret_cast<__half2*>(&ua.y));
            float2 fb0 = __half22float2(*reinterpret_cast<__half2*>(&ub.x));
            float2 fb1 = __half22float2(*reinterpret_cast<__half2*>(&ub.y));
            sum.x += fa0.x + fb0.x; sum.y += fa0.y + fb0.y;
            sum.z += fa1.x + fb1.x; sum.w += fa1.y + fb1.y;
        }
        if (e < s1) {
            int sa = __ldg(csr + e);
            uint2 ua = *reinterpret_cast<const uint2*>(h + (size_t)sa * DDIM + lane * 4);
            float2 fa0 = __half22float2(*reinterpret_cast<__half2*>(&ua.x));
            float2 fa1 = __half22float2(*reinterpret_cast<__half2*>(&ua.y));
            sum.x += fa0.x; sum.y += fa0.y; sum.z += fa1.x; sum.w += fa1.y;
        }
        float w  = __ldg(rdeg + base);
        float k0 = __ldg(coeff + r * NBASIS)     * w;
        float k1 = __ldg(coeff + r * NBASIS + 1) * w;
        a0.x += k0 * sum.x; a0.y += k0 * sum.y; a0.z += k0 * sum.z; a0.w += k0 * sum.w;
        a1.x += k1 * sum.x; a1.y += k1 * sum.y; a1.z += k1 * sum.z; a1.w += k1 * sum.w;
    }
    uint2 o0, o1;
    o0.x = pack_f16x2(make_float2(a0.x, a0.y));
    o0.y = pack_f16x2(make_float2(a0.z, a0.w));
    o1.x = pack_f16x2(make_float2(a1.x, a1.y));
    o1.y = pack_f16x2(make_float2(a1.z, a1.w));
    *reinterpret_cast<uint2*>(c0 + (size_t)gw * DDIM + lane * 4) = o0;
    *reinterpret_cast<uint2*>(c1 + (size_t)gw * DDIM + lane * 4) = o1;
}

// ---------------- launch ----------------------------------------------------------
extern "C" void kernel_launch(void* const* d_in, const int* in_sizes, int n_in,
                              void* d_out, int out_size) {
    const float* x        = (const float*)d_in[0];
    const int*   edge_src = (const int*)  d_in[1];
    const int*   edge_dst = (const int*)  d_in[2];
    const float* proj_w   = (const float*)d_in[3];
    const float* proj_b   = (const float*)d_in[4];
    const float* basis1   = (const float*)d_in[5];
    const float* coeff1   = (const float*)d_in[6];
    const float* bias1    = (const float*)d_in[7];
    const float* loop1    = (const float*)d_in[8];
    const float* basis2   = (const float*)d_in[9];
    const float* coeff2   = (const float*)d_in[10];
    const float* bias2    = (const float*)d_in[11];
    const float* loop2    = (const float*)d_in[12];
    float* out = (float*)d_out;

    float *rdeg;
    int *deg, *off, *cur, *part, *csr;
    __half *h0f, *h1f, *c0f, *c1f, *wthi, *pwhi;
    cudaGetSymbolAddress((void**)&h0f,  g_h0f);
    cudaGetSymbolAddress((void**)&h1f,  g_h1f);
    cudaGetSymbolAddress((void**)&c0f,  g_c0f);
    cudaGetSymbolAddress((void**)&c1f,  g_c1f);
    cudaGetSymbolAddress((void**)&rdeg, g_rdeg);
    cudaGetSymbolAddress((void**)&deg,  g_deg);
    cudaGetSymbolAddress((void**)&off,  g_off);
    cudaGetSymbolAddress((void**)&cur,  g_cur);
    cudaGetSymbolAddress((void**)&part, g_part);
    cudaGetSymbolAddress((void**)&csr,  g_csr);
    cudaGetSymbolAddress((void**)&wthi, g_wthi);
    cudaGetSymbolAddress((void**)&pwhi, g_pwhi);

    cudaFuncSetAttribute(tc_gemm<false, 1, true,  true >,
                         cudaFuncAttributeMaxDynamicSharedMemorySize, SMEM_PROJ);
    cudaFuncSetAttribute(tc_gemm<true, 3, false, true >,
                         cudaFuncAttributeMaxDynamicSharedMemorySize, SMEM_LAYER);
    cudaFuncSetAttribute(tc_gemm<true, 3, false, false>,
                         cudaFuncAttributeMaxDynamicSharedMemorySize, SMEM_LAYER);

    const int grid_n    = (NNODES + 127) / 128;             // 782
    const int wt_blocks = (128 * 384 + 255) / 256;          // 192

    // 1. proj weights (fp16) + deg zero (fused trivial kernels)
    wtproj_zero<<<PWT_BLOCKS + ZERO_BLOCKS, 256>>>(proj_w, pwhi, deg);
    // 2. degree histogram
    deg_count_kernel<<<(RE + 255) / 256, 256>>>(edge_dst, deg);
    // 3. projection GEMM: h0f = fp16(x @ proj_w + proj_b)
    tc_gemm<false, 1, true, true><<<grid_n, 128, SMEM_PROJ>>>(
        x, nullptr, nullptr, nullptr, pwhi, proj_b, nullptr, h0f, NNODES);
    // 4-6. CSR build
    scan_reduce<<<SCAN_BLOCKS, 256>>>(deg, part, RN);
    scan_final2<<<SCAN_BLOCKS, 256>>>(deg, part, off, cur, rdeg, RN, SCAN_BLOCKS);
    fill_csr<<<(RE + 255) / 256, 256>>>(edge_src, edge_dst, cur, csr);

    // ---- layer 1 ----
    gather_combo_wt<<<GATHER_BLOCKS + wt_blocks, 256>>>(h0f, off, csr, rdeg, coeff1,
                                                        c0f, c1f, basis1, loop1, wthi);
    tc_gemm<true, 3, false, true><<<grid_n, 128, SMEM_LAYER>>>(
        nullptr, c0f, c1f, h0f, wthi, bias1, nullptr, h1f, NNODES);

    // ---- layer 2 ----
    gather_combo_wt<<<GATHER_BLOCKS + wt_blocks, 256>>>(h1f, off, csr, rdeg, coeff2,
                                                        c0f, c1f, basis2, loop2, wthi);
    tc_gemm<true, 3, false, false><<<grid_n, 128, SMEM_LAYER>>>(
        nullptr, c0f, c1f, h1f, wthi, bias2, out, nullptr, NNODES);
}

// round 17
// speedup vs baseline: 1.0671x; 1.0055x over previous
#include <cuda_runtime.h>
#include <cuda_fp16.h>
#include <cstdint>

// Problem constants
#define NNODES 100000
#define DDIM   128
#define RREL   3
#define EEDGES 500000
#define NBASIS 2
#define RN     (RREL * NNODES)
#define RE     (RREL * EEDGES)

// ---------------- scratch (device globals) ----------------------------------
__device__ __half g_h0f[(size_t)NNODES * DDIM];   // activations, fp16
__device__ __half g_h1f[(size_t)NNODES * DDIM];
__device__ __half g_c0f[(size_t)NNODES * DDIM];   // basis combos, fp16
__device__ __half g_c1f[(size_t)NNODES * DDIM];
__device__ float g_rdeg[RN];
__device__ int   g_deg [RN];
__device__ int   g_off [RN + 1];
__device__ int   g_cur [RN];
__device__ int   g_part[1024];
__device__ int   g_csr [RE];
__device__ __half g_wthi[128 * 384];   // layer weights [o][k], fp16
__device__ __half g_pwhi[128 * 128];   // proj weights [o][k], fp16

// ---------------- smem geometry -----------------------------------------------
#define B_PITCH 144
#define B_TILE (128 * B_PITCH)                 // 18432
#define A_PITCH_F 72
#define A_TILE_F32 (128 * A_PITCH_F * 4)       // 36864
#define SMEM_PROJ  (2 * A_TILE_F32 + B_TILE)   // 92160
#define SMEM_LAYER (3 * B_TILE)                // 55296

__device__ __forceinline__ uint32_t smem_u32(const void* p) {
    uint32_t a;
    asm("{ .reg .u64 t; cvta.to.shared.u64 t, %1; cvt.u32.u64 %0, t; }" : "=r"(a) : "l"(p));
    return a;
}

__device__ __forceinline__ void cp_async16(uint32_t dst, const void* src, uint32_t sz) {
    asm volatile("cp.async.cg.shared.global [%0], [%1], 16, %2;"
                 :: "r"(dst), "l"(src), "r"(sz));
}
#define CP_COMMIT()  asm volatile("cp.async.commit_group;" ::: "memory")
#define CP_WAIT(n)   asm volatile("cp.async.wait_group %0;" :: "n"(n) : "memory")

__device__ __forceinline__ void mma16816h(float* c, const uint32_t* a, const uint32_t* b) {
    asm volatile(
        "mma.sync.aligned.m16n8k16.row.col.f32.f16.f16.f32 "
        "{%0,%1,%2,%3}, {%4,%5,%6,%7}, {%8,%9}, {%0,%1,%2,%3};\n"
        : "+f"(c[0]), "+f"(c[1]), "+f"(c[2]), "+f"(c[3])
        : "r"(a[0]), "r"(a[1]), "r"(a[2]), "r"(a[3]), "r"(b[0]), "r"(b[1]));
}

__device__ __forceinline__ uint32_t pack_f16x2(float2 f) {
    uint32_t r;
    asm("cvt.rn.f16x2.f32 %0, %1, %2;" : "=r"(r) : "f"(f.y), "f"(f.x));
    return r;
}

// ---------------- fp16 tensor-core GEMM (single W product) ----------------------
template <bool RELU, int NSEG, bool F32A, bool OUTF16>
__global__ __launch_bounds__(128, 2)
void tc_gemm(const float* __restrict__ Af,
             const __half* __restrict__ A0, const __half* __restrict__ A1,
             const __half* __restrict__ A2,
             const __half* __restrict__ whi,
             const float* __restrict__ bias, float* __restrict__ C,
             __half* __restrict__ Cf, int nrows) {
    extern __shared__ char smem[];
    constexpr int ATILE   = F32A ? A_TILE_F32 : B_TILE;
    constexpr int OFF_A1_ = ATILE;
    constexpr int OFF_BH  = 2 * ATILE;
    const uint32_t sbase = smem_u32(smem);
    const int tid  = threadIdx.x;
    const int wid  = tid >> 5;
    const int lane = tid & 31;
    const int wm = wid & 1;
    const int wn = wid >> 1;
    const int g  = lane >> 2;
    const int tg = lane & 3;
    const int n0 = blockIdx.x * 128;
    const int KSTRIDE = NSEG * 128;
    const __half* Aseg[3] = {A0, A1, A2};
    const int NCHUNK = 2 * NSEG;

    float acc[4][8][4];
#pragma unroll
    for (int mt = 0; mt < 4; mt++)
#pragma unroll
        for (int nt = 0; nt < 8; nt++)
#pragma unroll
            for (int j = 0; j < 4; j++) acc[mt][nt][j] = 0.f;

    auto load_A = [&](int cc) {
        const int kc = (cc & 1) * 64;
        uint32_t dbase = sbase + ((cc & 1) ? OFF_A1_ : 0);
        if constexpr (F32A) {
#pragma unroll
            for (int i = 0; i < 16; ++i) {
                int idx = i * 128 + tid;
                int row = idx >> 4;
                int q   = idx & 15;
                int n = n0 + row;
                bool valid = (n < nrows);
                const float* src = Af + (size_t)(valid ? n : 0) * DDIM + kc + q * 4;
                cp_async16(dbase + row * (A_PITCH_F * 4) + q * 16, src, valid ? 16u : 0u);
            }
        } else {
            const __half* A = Aseg[cc >> 1];
#pragma unroll
            for (int i = 0; i < 8; ++i) {
                int idx = i * 128 + tid;
                int row = idx >> 3;
                int q   = idx & 7;
                int n = n0 + row;
                bool valid = (n < nrows);
                const __half* src = A + (size_t)(valid ? n : 0) * DDIM + kc + q * 8;
                cp_async16(dbase + row * B_PITCH + q * 16, src, valid ? 16u : 0u);
            }
        }
    };

    auto load_B = [&](int cc) {
#pragma unroll
        for (int i = 0; i < 8; ++i) {
            int idx = i * 128 + tid;
            int n = idx >> 3;
            int q = idx & 7;
            size_t goff = (size_t)n * KSTRIDE + cc * 64 + q * 8;
            cp_async16(sbase + OFF_BH + n * B_PITCH + q * 16, whi + goff, 16);
        }
    };

    const int arow_f = (wm * 64 + g) * A_PITCH_F + 2 * tg;
    const int arow_b = (wm * 64 + g) * B_PITCH + tg * 4;
    const int brow   = (wn * 64 + g) * B_PITCH + tg * 4;

    load_A(0);
    CP_COMMIT();

#pragma unroll 1
    for (int c = 0; c < NCHUNK; ++c) {
        load_B(c);
        CP_COMMIT();
        if (c + 1 < NCHUNK) {
            load_A(c + 1);
            CP_COMMIT();
            CP_WAIT(1);
        } else {
            CP_WAIT(0);
        }
        __syncthreads();

        const char* Ab = smem + ((c & 1) ? OFF_A1_ : 0);

#pragma unroll
        for (int ks = 0; ks < 4; ++ks) {
            uint32_t a[4][4], bfr[8][2];
            if constexpr (F32A) {
#pragma unroll
                for (int mt = 0; mt < 4; ++mt) {
                    int fb = arow_f + mt * 16 * A_PITCH_F + ks * 16;
                    float2 f0 = *reinterpret_cast<const float2*>(Ab + fb * 4);
                    float2 f1 = *reinterpret_cast<const float2*>(Ab + (fb + 8 * A_PITCH_F) * 4);
                    float2 f2 = *reinterpret_cast<const float2*>(Ab + (fb + 8) * 4);
                    float2 f3 = *reinterpret_cast<const float2*>(Ab + (fb + 8 * A_PITCH_F + 8) * 4);
                    a[mt][0] = pack_f16x2(f0);
                    a[mt][1] = pack_f16x2(f1);
                    a[mt][2] = pack_f16x2(f2);
                    a[mt][3] = pack_f16x2(f3);
                }
            } else {
#pragma unroll
                for (int mt = 0; mt < 4; ++mt) {
                    int bb = arow_b + mt * 16 * B_PITCH + ks * 32;
                    a[mt][0] = *(const uint32_t*)(Ab + bb);
                    a[mt][1] = *(const uint32_t*)(Ab + bb + 8 * B_PITCH);
                    a[mt][2] = *(const uint32_t*)(Ab + bb + 16);
                    a[mt][3] = *(const uint32_t*)(Ab + bb + 8 * B_PITCH + 16);
                }
            }
#pragma unroll
            for (int nt = 0; nt < 8; ++nt) {
                int bb = brow + nt * (8 * B_PITCH) + ks * 32;
                bfr[nt][0] = *(const uint32_t*)(smem + OFF_BH + bb);
                bfr[nt][1] = *(const uint32_t*)(smem + OFF_BH + bb + 16);
            }
#pragma unroll
            for (int mt = 0; mt < 4; ++mt)
#pragma unroll
                for (int nt = 0; nt < 8; ++nt)
                    mma16816h(acc[mt][nt], a[mt], bfr[nt]);
        }
        __syncthreads();
    }

    // ---- epilogue: bias + relu ----
#pragma unroll
    for (int nt = 0; nt < 8; ++nt) {
        int col = wn * 64 + nt * 8 + 2 * tg;
        float bz0 = __ldg(bias + col);
        float bz1 = __ldg(bias + col + 1);
#pragma unroll
        for (int mt = 0; mt < 4; ++mt) {
            int row0 = n0 + wm * 64 + mt * 16 + g;
            int row1 = row0 + 8;
            float v0 = acc[mt][nt][0] + bz0, v1 = acc[mt][nt][1] + bz1;
            float v2 = acc[mt][nt][2] + bz0, v3 = acc[mt][nt][3] + bz1;
            if (RELU) {
                v0 = fmaxf(v0, 0.f); v1 = fmaxf(v1, 0.f);
                v2 = fmaxf(v2, 0.f); v3 = fmaxf(v3, 0.f);
            }
            if (row0 < nrows) {
                if constexpr (OUTF16)
                    *reinterpret_cast<uint32_t*>(Cf + (size_t)row0 * DDIM + col) =
                        pack_f16x2(make_float2(v0, v1));
                else
                    *reinterpret_cast<float2*>(C + (size_t)row0 * DDIM + col) = make_float2(v0, v1);
            }
            if (row1 < nrows) {
                if constexpr (OUTF16)
                    *reinterpret_cast<uint32_t*>(Cf + (size_t)row1 * DDIM + col) =
                        pack_f16x2(make_float2(v2, v3));
                else
                    *reinterpret_cast<float2*>(C + (size_t)row1 * DDIM + col) = make_float2(v2, v3);
            }
        }
    }
}

// ---------------- fused: proj weight build (fp16) + deg zero --------------------
#define PWT_BLOCKS 64                               // 128*128 / 256
#define ZERO_BLOCKS ((RN + 2047) / 2048)            // 147
__global__ void wtproj_zero(const float* __restrict__ projw,
                            __half* __restrict__ pwhi, int* __restrict__ deg) {
    int b = blockIdx.x;
    if (b < PWT_BLOCKS) {
        int i = b * 256 + threadIdx.x;
        int o = i >> 7;
        int k = i & 127;
        pwhi[i] = __float2half_rn(projw[k * DDIM + o]);
        return;
    }
    int base = (b - PWT_BLOCKS) * 2048 + threadIdx.x;
#pragma unroll
    for (int j = 0; j < 8; ++j) {
        int i = base + j * 256;
        if (i < RN) deg[i] = 0;
    }
}

// vectorized: each thread reads 4 dst ids (one int4); 4-pack never crosses a
// relation boundary (EEDGES % 4 == 0).
__global__ void deg_count_kernel(const int* __restrict__ dst, int* __restrict__ deg) {
    int t = blockIdx.x * blockDim.x + threadIdx.x;
    int i4 = t * 4;
    if (i4 >= RE) return;
    int4 d = *reinterpret_cast<const int4*>(dst + i4);
    int rbase = (i4 >= 2 * EEDGES ? 2 : (i4 >= EEDGES ? 1 : 0)) * NNODES;
    atomicAdd(&deg[rbase + d.x], 1);
    atomicAdd(&deg[rbase + d.y], 1);
    atomicAdd(&deg[rbase + d.z], 1);
    atomicAdd(&deg[rbase + d.w], 1);
}

// ---------------- scan: 2 kernels ------------------------------------------------
#define SCAN_BLOCKS ((RN + 1023) / 1024)            // 293

__global__ void scan_reduce(const int* __restrict__ deg, int* __restrict__ part, int n) {
    __shared__ int sm[256];
    int b = blockIdx.x, t = threadIdx.x;
    int i0 = b * 1024 + t * 4;
    int s = 0;
#pragma unroll
    for (int j = 0; j < 4; ++j) { int i = i0 + j; if (i < n) s += deg[i]; }
    sm[t] = s; __syncthreads();
    for (int st = 128; st > 0; st >>= 1) { if (t < st) sm[t] += sm[t + st]; __syncthreads(); }
    if (t == 0) part[b] = sm[0];
}

__global__ void scan_final2(const int* __restrict__ deg, const int* __restrict__ part,
                            int* __restrict__ off, int* __restrict__ cur,
                            float* __restrict__ rdeg, int n, int nblocks) {
    __shared__ int sp[256];
    __shared__ int sm[256];
    int b = blockIdx.x, t = threadIdx.x;
    if (b == 0 && t == 0) off[RN] = RE;
    int v0 = (t < nblocks && t < b) ? part[t] : 0;
    int v1 = (t + 256 < nblocks && t + 256 < b) ? part[t + 256] : 0;
    sp[t] = v0 + v1; __syncthreads();
    for (int st = 128; st > 0; st >>= 1) { if (t < st) sp[t] += sp[t + st]; __syncthreads(); }
    int base0 = sp[0];

    int i0 = b * 1024 + t * 4;
    int v[4]; int s = 0;
#pragma unroll
    for (int j = 0; j < 4; ++j) { int i = i0 + j; v[j] = (i < n) ? deg[i] : 0; s += v[j]; }
    sm[t] = s; __syncthreads();
    for (int st = 1; st < 256; st <<= 1) {
        int add = (t >= st) ? sm[t - st] : 0;
        __syncthreads();
        sm[t] += add;
        __syncthreads();
    }
    int base = base0 + sm[t] - s;
#pragma unroll
    for (int j = 0; j < 4; ++j) {
        int i = i0 + j;
        if (i < n) {
            off[i] = base; cur[i] = base; base += v[j];
            rdeg[i] = 1.0f / fmaxf((float)v[j], 1.0f);
        }
    }
}

// vectorized fill: int4 src/dst reads, compare-based relation id.
__global__ void fill_csr(const int* __restrict__ src, const int* __restrict__ dst,
                         int* __restrict__ cur, int* __restrict__ csr) {
    int t = blockIdx.x * blockDim.x + threadIdx.x;
    int i4 = t * 4;
    if (i4 >= RE) return;
    int4 s = *reinterpret_cast<const int4*>(src + i4);
    int4 d = *reinterpret_cast<const int4*>(dst + i4);
    int rbase = (i4 >= 2 * EEDGES ? 2 : (i4 >= EEDGES ? 1 : 0)) * NNODES;
    csr[atomicAdd(&cur[rbase + d.x], 1)] = s.x;
    csr[atomicAdd(&cur[rbase + d.y], 1)] = s.y;
    csr[atomicAdd(&cur[rbase + d.z], 1)] = s.z;
    csr[atomicAdd(&cur[rbase + d.w], 1)] = s.w;
}

// ---------------- gather-aggregate (pipelined csr-index stream) -----------------
#define GATHER_BLOCKS ((NNODES * 32 + 255) / 256)
__global__ __launch_bounds__(256)
void gather_combo_wt(const __half* __restrict__ h, const int* __restrict__ off,
                     const int* __restrict__ csr, const float* __restrict__ rdeg,
                     const float* __restrict__ coeff,
                     __half* __restrict__ c0, __half* __restrict__ c1,
                     const float* __restrict__ basis, const float* __restrict__ loopw,
                     __half* __restrict__ whi) {
    int b = blockIdx.x;
    if (b >= GATHER_BLOCKS) {
        int i = (b - GATHER_BLOCKS) * 256 + threadIdx.x;   // 128*384
        if (i < 128 * 384) {
            int o = i / 384;
            int k = i - o * 384;
            int seg = k >> 7;
            int kk = k & 127;
            float v = (seg < 2) ? basis[(size_t)seg * DDIM * DDIM + kk * DDIM + o]
                                : loopw[kk * DDIM + o];
            whi[i] = __float2half_rn(v);
        }
        return;
    }
    int gw = (int)(((unsigned)b * 256u + threadIdx.x) >> 5);
    int lane = threadIdx.x & 31;
    if (gw >= NNODES) return;

    // hoisted bounds + weights + first-index prefetch for all 3 relations
    int s0[3], s1[3], pre[3];
    float wgt[3];
#pragma unroll
    for (int r = 0; r < RREL; ++r) {
        int base = r * NNODES + gw;
        s0[r] = __ldg(off + base);
        s1[r] = __ldg(off + base + 1);
        wgt[r] = __ldg(rdeg + base);
    }
#pragma unroll
    for (int r = 0; r < RREL; ++r)
        pre[r] = (s0[r] < s1[r]) ? __ldg(csr + s0[r]) : 0;

    float4 a0 = make_float4(0.f, 0.f, 0.f, 0.f);
    float4 a1 = a0;
#pragma unroll
    for (int r = 0; r < RREL; ++r) {
        int e = s0[r], end = s1[r];
        int nxt = pre[r];
        float4 sum = make_float4(0.f, 0.f, 0.f, 0.f);
        while (e + 2 <= end) {
            int sa = nxt;
            int sb = __ldg(csr + e + 1);
            e += 2;
            if (e < end) nxt = __ldg(csr + e);   // pipeline next pair's index
            uint2 ua = *reinterpret_cast<const uint2*>(h + (size_t)sa * DDIM + lane * 4);
            uint2 ub = *reinterpret_cast<const uint2*>(h + (size_t)sb * DDIM + lane * 4);
            float2 fa0 = __half22float2(*reinterpret_cast<__half2*>(&ua.x));
            float2 fa1 = __half22float2(*reinterpret_cast<__half2*>(&ua.y));
            float2 fb0 = __half22float2(*reinterpret_cast<__half2*>(&ub.x));
            float2 fb1 = __half22float2(*reinterpret_cast<__half2*>(&ub.y));
            sum.x += fa0.x + fb0.x; sum.y += fa0.y + fb0.y;
            sum.z += fa1.x + fb1.x; sum.w += fa1.y + fb1.y;
        }
        if (e < end) {
            int sa = nxt;                         // deg odd: nxt holds csr[e]
            uint2 ua = *reinterpret_cast<const uint2*>(h + (size_t)sa * DDIM + lane * 4);
            float2 fa0 = __half22float2(*reinterpret_cast<__half2*>(&ua.x));
            float2 fa1 = __half22float2(*reinterpret_cast<__half2*>(&ua.y));
            sum.x += fa0.x; sum.y += fa0.y; sum.z += fa1.x; sum.w += fa1.y;
        }
        float k0 = __ldg(coeff + r * NBASIS)     * wgt[r];
        float k1 = __ldg(coeff + r * NBASIS + 1) * wgt[r];
        a0.x += k0 * sum.x; a0.y += k0 * sum.y; a0.z += k0 * sum.z; a0.w += k0 * sum.w;
        a1.x += k1 * sum.x; a1.y += k1 * sum.y; a1.z += k1 * sum.z; a1.w += k1 * sum.w;
    }
    uint2 o0, o1;
    o0.x = pack_f16x2(make_float2(a0.x, a0.y));
    o0.y = pack_f16x2(make_float2(a0.z, a0.w));
    o1.x = pack_f16x2(make_float2(a1.x, a1.y));
    o1.y = pack_f16x2(make_float2(a1.z, a1.w));
    *reinterpret_cast<uint2*>(c0 + (size_t)gw * DDIM + lane * 4) = o0;
    *reinterpret_cast<uint2*>(c1 + (size_t)gw * DDIM + lane * 4) = o1;
}

// ---------------- launch ----------------------------------------------------------
extern "C" void kernel_launch(void* const* d_in, const int* in_sizes, int n_in,
                              void* d_out, int out_size) {
    const float* x        = (const float*)d_in[0];
    const int*   edge_src = (const int*)  d_in[1];
    const int*   edge_dst = (const int*)  d_in[2];
    const float* proj_w   = (const float*)d_in[3];
    const float* proj_b   = (const float*)d_in[4];
    const float* basis1   = (const float*)d_in[5];
    const float* coeff1   = (const float*)d_in[6];
    const float* bias1    = (const float*)d_in[7];
    const float* loop1    = (const float*)d_in[8];
    const float* basis2   = (const float*)d_in[9];
    const float* coeff2   = (const float*)d_in[10];
    const float* bias2    = (const float*)d_in[11];
    const float* loop2    = (const float*)d_in[12];
    float* out = (float*)d_out;

    float *rdeg;
    int *deg, *off, *cur, *part, *csr;
    __half *h0f, *h1f, *c0f, *c1f, *wthi, *pwhi;
    cudaGetSymbolAddress((void**)&h0f,  g_h0f);
    cudaGetSymbolAddress((void**)&h1f,  g_h1f);
    cudaGetSymbolAddress((void**)&c0f,  g_c0f);
    cudaGetSymbolAddress((void**)&c1f,  g_c1f);
    cudaGetSymbolAddress((void**)&rdeg, g_rdeg);
    cudaGetSymbolAddress((void**)&deg,  g_deg);
    cudaGetSymbolAddress((void**)&off,  g_off);
    cudaGetSymbolAddress((void**)&cur,  g_cur);
    cudaGetSymbolAddress((void**)&part, g_part);
    cudaGetSymbolAddress((void**)&csr,  g_csr);
    cudaGetSymbolAddress((void**)&wthi, g_wthi);
    cudaGetSymbolAddress((void**)&pwhi, g_pwhi);

    cudaFuncSetAttribute(tc_gemm<false, 1, true,  true >,
                         cudaFuncAttributeMaxDynamicSharedMemorySize, SMEM_PROJ);
    cudaFuncSetAttribute(tc_gemm<true, 3, false, true >,
                         cudaFuncAttributeMaxDynamicSharedMemorySize, SMEM_LAYER);
    cudaFuncSetAttribute(tc_gemm<true, 3, false, false>,
                         cudaFuncAttributeMaxDynamicSharedMemorySize, SMEM_LAYER);

    const int grid_n    = (NNODES + 127) / 128;             // 782
    const int wt_blocks = (128 * 384 + 255) / 256;          // 192
    const int e4_blocks = (RE / 4 + 255) / 256;             // 1465

    // 1. proj weights (fp16) + deg zero
    wtproj_zero<<<PWT_BLOCKS + ZERO_BLOCKS, 256>>>(proj_w, pwhi, deg);
    // 2. degree histogram (int4)
    deg_count_kernel<<<e4_blocks, 256>>>(edge_dst, deg);
    // 3. projection GEMM
    tc_gemm<false, 1, true, true><<<grid_n, 128, SMEM_PROJ>>>(
        x, nullptr, nullptr, nullptr, pwhi, proj_b, nullptr, h0f, NNODES);
    // 4-6. CSR build
    scan_reduce<<<SCAN_BLOCKS, 256>>>(deg, part, RN);
    scan_final2<<<SCAN_BLOCKS, 256>>>(deg, part, off, cur, rdeg, RN, SCAN_BLOCKS);
    fill_csr<<<e4_blocks, 256>>>(edge_src, edge_dst, cur, csr);

    // ---- layer 1 ----
    gather_combo_wt<<<GATHER_BLOCKS + wt_blocks, 256>>>(h0f, off, csr, rdeg, coeff1,
                                                        c0f, c1f, basis1, loop1, wthi);
    tc_gemm<true, 3, false, true><<<grid_n, 128, SMEM_LAYER>>>(
        nullptr, c0f, c1f, h0f, wthi, bias1, nullptr, h1f, NNODES);

    // ---- layer 2 ----
    gather_combo_wt<<<GATHER_BLOCKS + wt_blocks, 256>>>(h1f, off, csr, rdeg, coeff2,
                                                        c0f, c1f, basis2, loop2, wthi);
    tc_gemm<true, 3, false, false><<<grid_n, 128, SMEM_LAYER>>>(
        nullptr, c0f, c1f, h1f, wthi, bias2, out, nullptr, NNODES);
}